// round 1
// baseline (speedup 1.0000x reference)
#include <cuda_runtime.h>
#include <cstdint>

#define BATCH 4
#define CIN   64
#define HIN   128
#define WIN   128
#define COUT  64
#define GHH   256
#define GWW   256

// Scratch (static device allocations are allowed)
__device__ float g_kern[(size_t)BATCH * 9 * GHH * GWW];   // 9.4 MB
__device__ float g_wr[9 * CIN * COUT];                    // weight reorganized [tap][c][o]

// ---------------------------------------------------------------------------
// Pass 1: Gaussian affinity kernel  kern[b][t][h][w] = exp(-0.5*sum_g diff^2)
// ---------------------------------------------------------------------------
__global__ void kern_kernel(const float* __restrict__ guide) {
    int idx = blockIdx.x * blockDim.x + threadIdx.x;
    if (idx >= BATCH * GHH * GWW) return;
    int w = idx % GWW;
    int h = (idx / GWW) % GHH;
    int b = idx / (GHH * GWW);
    const float* gp = guide + (size_t)b * 3 * GHH * GWW;
    float c0 = gp[0 * GHH * GWW + h * GWW + w];
    float c1 = gp[1 * GHH * GWW + h * GWW + w];
    float c2 = gp[2 * GHH * GWW + h * GWW + w];
#pragma unroll
    for (int kh = 0; kh < 3; kh++) {
#pragma unroll
        for (int kw = 0; kw < 3; kw++) {
            int hh = h + kh - 1, ww = w + kw - 1;
            float v0 = 0.f, v1 = 0.f, v2 = 0.f;
            if (hh >= 0 && hh < GHH && ww >= 0 && ww < GWW) {
                v0 = gp[0 * GHH * GWW + hh * GWW + ww];
                v1 = gp[1 * GHH * GWW + hh * GWW + ww];
                v2 = gp[2 * GHH * GWW + hh * GWW + ww];
            }
            float d0 = v0 - c0, d1 = v1 - c1, d2 = v2 - c2;
            float s = d0 * d0 + d1 * d1 + d2 * d2;
            g_kern[(((size_t)b * 9 + kh * 3 + kw) * GHH + h) * GWW + w] = __expf(-0.5f * s);
        }
    }
}

// ---------------------------------------------------------------------------
// Pass 2: reorganize weight [c][o][kh][kw] -> [tap][c][o]
// ---------------------------------------------------------------------------
__global__ void wreorg_kernel(const float* __restrict__ wt) {
    int idx = blockIdx.x * blockDim.x + threadIdx.x;
    if (idx >= CIN * COUT * 9) return;
    int t = idx % 9;
    int o = (idx / 9) % COUT;
    int c = idx / (9 * COUT);
    g_wr[(t * CIN + c) * COUT + o] = wt[idx];
}

// ---------------------------------------------------------------------------
// Pass 3: per-parity-class implicit GEMM.
//   Block: one (class, batch, 8hh x 16ww tile) = 128 class-pixels, all 64 o.
//   Thread: 8 pixels x 8 out-channels, fp32x2-packed FFMA.
// ---------------------------------------------------------------------------
__global__ __launch_bounds__(128)
void pac_kernel(const float* __restrict__ x,
                const float* __restrict__ bias,
                float* __restrict__ out) {
    __shared__ __align__(16) float As[CIN][128];   // 32 KB  (A tile / C staging)
    __shared__ __align__(16) float Bs[CIN][COUT];  // 16 KB

    const int cls = blockIdx.z;
    const int ph = cls >> 1, pw = cls & 1;
    const int b = blockIdx.y;
    const int th = blockIdx.x >> 3;   // 0..15
    const int tw = blockIdx.x & 7;    // 0..7
    const int hh0 = th * 8, ww0 = tw * 16;

    const int t = threadIdx.x;
    const int og = t & 7;    // out-channel group (8 o each)
    const int pg = t >> 3;   // pixel group (8 px each)

    // pixel owned for A-build / epilogue: px == t
    const int hh_l = t >> 4, ww_l = t & 15;
    const int h = 2 * (hh0 + hh_l) + ph;
    const int w = 2 * (ww0 + ww_l) + pw;

    unsigned long long acc[4][8];  // [px-pair][o] packed f32x2
#pragma unroll
    for (int i = 0; i < 4; i++)
#pragma unroll
        for (int j = 0; j < 8; j++) acc[i][j] = 0ull;

    const int nkh = ph ? 2 : 1;
    const int nkw = pw ? 2 : 1;

    for (int ta = 0; ta < nkh; ta++) {
        const int kh = ph ? ta * 2 : 1;
        for (int tb = 0; tb < nkw; tb++) {
            const int kw = pw ? tb * 2 : 1;
            const int tap = kh * 3 + kw;

            // --- load B tile (weight slice for this tap) ---
            {
                const float4* src = (const float4*)(g_wr + (size_t)tap * CIN * COUT);
                float4* dst = (float4*)(&Bs[0][0]);
#pragma unroll
                for (int i = 0; i < 8; i++) dst[t + i * 128] = src[t + i * 128];
            }

            // --- build A tile: A[c][px] = kern[px,tap] * x[c, ih, iw] ---
            {
                const int ih = (h + kh - 1) >> 1;
                const int iw = (w + kw - 1) >> 1;
                if (ih < HIN && iw < WIN) {  // lower bound is guaranteed >= 0
                    const float kv =
                        g_kern[(((size_t)b * 9 + tap) * GHH + h) * GWW + w];
                    const float* xp =
                        x + (((size_t)b * CIN) * HIN + ih) * WIN + iw;
#pragma unroll 8
                    for (int c = 0; c < CIN; c++)
                        As[c][t] = kv * __ldg(xp + c * (HIN * WIN));
                } else {
#pragma unroll 8
                    for (int c = 0; c < CIN; c++) As[c][t] = 0.f;
                }
            }
            __syncthreads();

            // --- register-tiled GEMM accumulate: 8 px x 8 o per thread ---
#pragma unroll 8
            for (int c = 0; c < CIN; c++) {
                const ulonglong2* ap = (const ulonglong2*)&As[c][pg * 8];
                ulonglong2 a01 = ap[0];
                ulonglong2 a23 = ap[1];
                float4 b0 = *(const float4*)&Bs[c][og * 8];
                float4 b1 = *(const float4*)&Bs[c][og * 8 + 4];
                float bv[8] = {b0.x, b0.y, b0.z, b0.w, b1.x, b1.y, b1.z, b1.w};
#pragma unroll
                for (int j = 0; j < 8; j++) {
                    unsigned long long bb2;
                    unsigned int bu = __float_as_uint(bv[j]);
                    asm("mov.b64 %0, {%1, %2};" : "=l"(bb2) : "r"(bu), "r"(bu));
                    asm("fma.rn.f32x2 %0, %1, %2, %0;" : "+l"(acc[0][j]) : "l"(a01.x), "l"(bb2));
                    asm("fma.rn.f32x2 %0, %1, %2, %0;" : "+l"(acc[1][j]) : "l"(a01.y), "l"(bb2));
                    asm("fma.rn.f32x2 %0, %1, %2, %0;" : "+l"(acc[2][j]) : "l"(a23.x), "l"(bb2));
                    asm("fma.rn.f32x2 %0, %1, %2, %0;" : "+l"(acc[3][j]) : "l"(a23.y), "l"(bb2));
                }
            }
            __syncthreads();
        }
    }

    // --- epilogue: stage to smem (XOR-swizzled, conflict-free), coalesced store
    float* Cs = &As[0][0];  // reuse A tile: [o][128] with low-3-bit xor swizzle
#pragma unroll
    for (int pr = 0; pr < 4; pr++) {
#pragma unroll
        for (int j = 0; j < 8; j++) {
            const int o = og * 8 + j;
            const unsigned long long v = acc[pr][j];
            const float lo = __uint_as_float((unsigned int)v);
            const float hi = __uint_as_float((unsigned int)(v >> 32));
            const int px0 = pg * 8 + pr * 2;
            const int base = o * 128 + (px0 & ~7);
            Cs[base + (((px0) & 7) ^ og)] = lo;
            Cs[base + (((px0 + 1) & 7) ^ og)] = hi;
        }
    }
    __syncthreads();

#pragma unroll 4
    for (int o = 0; o < COUT; o++) {
        const int sw = o >> 3;
        const float v = Cs[o * 128 + (t & ~7) + ((t & 7) ^ sw)] + __ldg(bias + o);
        out[(((size_t)b * COUT + o) * GHH + h) * GWW + w] = v;
    }
}

// ---------------------------------------------------------------------------
extern "C" void kernel_launch(void* const* d_in, const int* in_sizes, int n_in,
                              void* d_out, int out_size) {
    const float* x      = (const float*)d_in[0];
    const float* guide  = (const float*)d_in[1];
    const float* weight = (const float*)d_in[2];
    const float* bias   = (const float*)d_in[3];
    float* out          = (float*)d_out;

    kern_kernel<<<(BATCH * GHH * GWW + 255) / 256, 256>>>(guide);
    wreorg_kernel<<<(CIN * COUT * 9 + 255) / 256, 256>>>(weight);

    dim3 grid(128, BATCH, 4);  // 16x8 tiles, batch, parity class
    pac_kernel<<<grid, 128>>>(x, bias, out);
}

// round 2
// speedup vs baseline: 1.0698x; 1.0698x over previous
#include <cuda_runtime.h>
#include <cstdint>

#define BATCH 4
#define CIN   64
#define HIN   128
#define WIN   128
#define COUT  64
#define GHH   256
#define GWW   256

// Scratch (static device allocations are allowed)
__device__ float g_kern[(size_t)BATCH * 9 * GHH * GWW];   // 9.4 MB
__device__ float g_wr[9 * CIN * COUT];                    // weight reorganized [tap][c][o]

// ---------------------------------------------------------------------------
// Pass 1: Gaussian affinity kernel  kern[b][t][h][w] = exp(-0.5*sum_g diff^2)
// ---------------------------------------------------------------------------
__global__ void kern_kernel(const float* __restrict__ guide) {
    int idx = blockIdx.x * blockDim.x + threadIdx.x;
    if (idx >= BATCH * GHH * GWW) return;
    int w = idx % GWW;
    int h = (idx / GWW) % GHH;
    int b = idx / (GHH * GWW);
    const float* gp = guide + (size_t)b * 3 * GHH * GWW;
    float c0 = gp[0 * GHH * GWW + h * GWW + w];
    float c1 = gp[1 * GHH * GWW + h * GWW + w];
    float c2 = gp[2 * GHH * GWW + h * GWW + w];
#pragma unroll
    for (int kh = 0; kh < 3; kh++) {
#pragma unroll
        for (int kw = 0; kw < 3; kw++) {
            int hh = h + kh - 1, ww = w + kw - 1;
            float v0 = 0.f, v1 = 0.f, v2 = 0.f;
            if (hh >= 0 && hh < GHH && ww >= 0 && ww < GWW) {
                v0 = gp[0 * GHH * GWW + hh * GWW + ww];
                v1 = gp[1 * GHH * GWW + hh * GWW + ww];
                v2 = gp[2 * GHH * GWW + hh * GWW + ww];
            }
            float d0 = v0 - c0, d1 = v1 - c1, d2 = v2 - c2;
            float s = d0 * d0 + d1 * d1 + d2 * d2;
            g_kern[(((size_t)b * 9 + kh * 3 + kw) * GHH + h) * GWW + w] = __expf(-0.5f * s);
        }
    }
}

// ---------------------------------------------------------------------------
// Pass 2: reorganize weight [c][o][kh][kw] -> [tap][c][o]
// ---------------------------------------------------------------------------
__global__ void wreorg_kernel(const float* __restrict__ wt) {
    int idx = blockIdx.x * blockDim.x + threadIdx.x;
    if (idx >= CIN * COUT * 9) return;
    int t = idx % 9;
    int o = (idx / 9) % COUT;
    int c = idx / (9 * COUT);
    g_wr[(t * CIN + c) * COUT + o] = wt[idx];
}

// ---------------------------------------------------------------------------
// Pass 3: per-parity-class implicit GEMM, LPT-ordered 1D grid.
//   Block: one (class, batch, 8hh x 16ww tile) = 128 class-pixels, all 64 o.
//   Thread: 8 pixels x 8 out-channels, fp32x2-packed FFMA.
//   Grid order: class 3 (4 taps) first, class 0 (1 tap) last -> no heavy tail.
// ---------------------------------------------------------------------------
__global__ __launch_bounds__(128)
void pac_kernel(const float* __restrict__ x,
                const float* __restrict__ bias,
                float* __restrict__ out) {
    __shared__ __align__(16) float As[CIN][128];   // 32 KB  (A tile / C staging)
    __shared__ __align__(16) float Bs[CIN][COUT];  // 16 KB

    // LPT ordering: chunk 0 -> class 3 (heaviest), chunk 3 -> class 0 (lightest)
    const int bid = blockIdx.x;
    const int cls = 3 - (bid >> 9);
    const int sub = bid & 511;
    const int b = sub >> 7;            // batch 0..3
    const int tile = sub & 127;        // 0..127

    const int ph = cls >> 1, pw = cls & 1;
    const int th = tile >> 3;   // 0..15
    const int tw = tile & 7;    // 0..7
    const int hh0 = th * 8, ww0 = tw * 16;

    const int t = threadIdx.x;
    const int og = t & 7;    // out-channel group (8 o each)
    const int pg = t >> 3;   // pixel group (8 px each)

    // pixel owned for A-build / epilogue: px == t
    const int hh_l = t >> 4, ww_l = t & 15;
    const int h = 2 * (hh0 + hh_l) + ph;
    const int w = 2 * (ww0 + ww_l) + pw;

    unsigned long long acc[4][8];  // [px-pair][o] packed f32x2
#pragma unroll
    for (int i = 0; i < 4; i++)
#pragma unroll
        for (int j = 0; j < 8; j++) acc[i][j] = 0ull;

    const int nkh = ph ? 2 : 1;
    const int nkw = pw ? 2 : 1;

    for (int ta = 0; ta < nkh; ta++) {
        const int kh = ph ? ta * 2 : 1;
        for (int tb = 0; tb < nkw; tb++) {
            const int kw = pw ? tb * 2 : 1;
            const int tap = kh * 3 + kw;

            // --- load B tile (weight slice for this tap) ---
            {
                const float4* src = (const float4*)(g_wr + (size_t)tap * CIN * COUT);
                float4* dst = (float4*)(&Bs[0][0]);
#pragma unroll
                for (int i = 0; i < 8; i++) dst[t + i * 128] = src[t + i * 128];
            }

            // --- build A tile: A[c][px] = kern[px,tap] * x[c, ih, iw] ---
            {
                const int ih = (h + kh - 1) >> 1;
                const int iw = (w + kw - 1) >> 1;
                if (ih < HIN && iw < WIN) {  // lower bound is guaranteed >= 0
                    const float kv =
                        g_kern[(((size_t)b * 9 + tap) * GHH + h) * GWW + w];
                    const float* xp =
                        x + (((size_t)b * CIN) * HIN + ih) * WIN + iw;
#pragma unroll 8
                    for (int c = 0; c < CIN; c++)
                        As[c][t] = kv * __ldg(xp + c * (HIN * WIN));
                } else {
#pragma unroll 8
                    for (int c = 0; c < CIN; c++) As[c][t] = 0.f;
                }
            }
            __syncthreads();

            // --- register-tiled GEMM accumulate: 8 px x 8 o per thread ---
#pragma unroll 8
            for (int c = 0; c < CIN; c++) {
                const ulonglong2* ap = (const ulonglong2*)&As[c][pg * 8];
                ulonglong2 a01 = ap[0];
                ulonglong2 a23 = ap[1];
                float4 b0 = *(const float4*)&Bs[c][og * 8];
                float4 b1 = *(const float4*)&Bs[c][og * 8 + 4];
                float bv[8] = {b0.x, b0.y, b0.z, b0.w, b1.x, b1.y, b1.z, b1.w};
#pragma unroll
                for (int j = 0; j < 8; j++) {
                    unsigned long long bb2;
                    unsigned int bu = __float_as_uint(bv[j]);
                    asm("mov.b64 %0, {%1, %2};" : "=l"(bb2) : "r"(bu), "r"(bu));
                    asm("fma.rn.f32x2 %0, %1, %2, %0;" : "+l"(acc[0][j]) : "l"(a01.x), "l"(bb2));
                    asm("fma.rn.f32x2 %0, %1, %2, %0;" : "+l"(acc[1][j]) : "l"(a01.y), "l"(bb2));
                    asm("fma.rn.f32x2 %0, %1, %2, %0;" : "+l"(acc[2][j]) : "l"(a23.x), "l"(bb2));
                    asm("fma.rn.f32x2 %0, %1, %2, %0;" : "+l"(acc[3][j]) : "l"(a23.y), "l"(bb2));
                }
            }
            __syncthreads();
        }
    }

    // --- epilogue: stage to smem (XOR-swizzled, conflict-free), coalesced store
    float* Cs = &As[0][0];  // reuse A tile: [o][128] with low-3-bit xor swizzle
#pragma unroll
    for (int pr = 0; pr < 4; pr++) {
#pragma unroll
        for (int j = 0; j < 8; j++) {
            const int o = og * 8 + j;
            const unsigned long long v = acc[pr][j];
            const float lo = __uint_as_float((unsigned int)v);
            const float hi = __uint_as_float((unsigned int)(v >> 32));
            const int px0 = pg * 8 + pr * 2;
            const int base = o * 128 + (px0 & ~7);
            Cs[base + (((px0) & 7) ^ og)] = lo;
            Cs[base + (((px0 + 1) & 7) ^ og)] = hi;
        }
    }
    __syncthreads();

#pragma unroll 4
    for (int o = 0; o < COUT; o++) {
        const int sw = o >> 3;
        const float v = Cs[o * 128 + (t & ~7) + ((t & 7) ^ sw)] + __ldg(bias + o);
        out[(((size_t)b * COUT + o) * GHH + h) * GWW + w] = v;
    }
}

// ---------------------------------------------------------------------------
extern "C" void kernel_launch(void* const* d_in, const int* in_sizes, int n_in,
                              void* d_out, int out_size) {
    const float* x      = (const float*)d_in[0];
    const float* guide  = (const float*)d_in[1];
    const float* weight = (const float*)d_in[2];
    const float* bias   = (const float*)d_in[3];
    float* out          = (float*)d_out;

    kern_kernel<<<(BATCH * GHH * GWW + 255) / 256, 256>>>(guide);
    wreorg_kernel<<<(CIN * COUT * 9 + 255) / 256, 256>>>(weight);

    pac_kernel<<<2048, 128>>>(x, bias, out);
}

// round 4
// speedup vs baseline: 1.6543x; 1.5464x over previous
#include <cuda_runtime.h>
#include <cuda_fp16.h>
#include <cstdint>

#define BATCH 4
#define CIN   64
#define COUT  64
#define HIN   128
#define WIN   128
#define GHH   256
#define GWW   256
#define HW    (HIN * WIN)

// Scratch
__device__ float  g_kern[(size_t)BATCH * 9 * GHH * GWW];  // Gaussian affinities (valid-parity entries only)
__device__ __half g_wb[9 * 128 * 64];                     // per-tap B image: [k rows: 0-63 hi | 64-127 lo][n=64], 128B rows, XOR-swizzled

// ---------------------------------------------------------------------------
// Prep: blocks [0,1024) -> Gaussian kernel (only parity-valid taps);
//       blocks [1024,1168) -> split-fp16 weight images
// ---------------------------------------------------------------------------
__global__ void prep_kernel(const float* __restrict__ guide,
                            const float* __restrict__ weight) {
    if (blockIdx.x < 1024) {
        int idx = blockIdx.x * 256 + threadIdx.x;
        int w = idx % GWW;
        int h = (idx / GWW) % GHH;
        int b = idx / (GHH * GWW);
        const float* gp = guide + (size_t)b * 3 * GHH * GWW;
        float c0 = gp[0 * GHH * GWW + h * GWW + w];
        float c1 = gp[1 * GHH * GWW + h * GWW + w];
        float c2 = gp[2 * GHH * GWW + h * GWW + w];
#pragma unroll
        for (int kh = 0; kh < 3; kh++) {
#pragma unroll
            for (int kw = 0; kw < 3; kw++) {
                if ((((h + kh) & 1) == 0) || (((w + kw) & 1) == 0)) continue;  // tap never used
                int hh = h + kh - 1, ww = w + kw - 1;
                float v0 = 0.f, v1 = 0.f, v2 = 0.f;
                if (hh >= 0 && hh < GHH && ww >= 0 && ww < GWW) {
                    v0 = gp[0 * GHH * GWW + hh * GWW + ww];
                    v1 = gp[1 * GHH * GWW + hh * GWW + ww];
                    v2 = gp[2 * GHH * GWW + hh * GWW + ww];
                }
                float d0 = v0 - c0, d1 = v1 - c1, d2 = v2 - c2;
                float s = d0 * d0 + d1 * d1 + d2 * d2;
                g_kern[(((size_t)b * 9 + kh * 3 + kw) * GHH + h) * GWW + w] = __expf(-0.5f * s);
            }
        }
    } else {
        int idx = (blockIdx.x - 1024) * 256 + threadIdx.x;
        if (idx < 9 * 64 * 64) {
            int tap = idx % 9;
            int o = (idx / 9) & 63;
            int c = idx / (9 * 64);
            float wv = weight[((size_t)c * COUT + o) * 9 + tap];
            __half bh = __float2half_rn(wv);
            __half bl = __float2half_rn(wv - __half2float(bh));
            // B image: [k-row][n], 128B rows, byte-in-row = (2o) ^ ((krow&7)<<4)
            char* p = (char*)g_wb + (size_t)tap * (128 * 64 * 2);
            uint32_t col = ((uint32_t)o * 2) ^ (((uint32_t)c & 7) << 4);
            *(__half*)(p + (uint32_t)c * 128 + col) = bh;            // hi plane rows 0-63
            *(__half*)(p + (uint32_t)(c + 64) * 128 + col) = bl;     // lo plane rows 64-127
        }
    }
}

// ---------------------------------------------------------------------------
// mma helpers
// ---------------------------------------------------------------------------
__device__ __forceinline__ uint32_t smem_u32(const void* p) {
    uint32_t a;
    asm("{ .reg .u64 t; cvta.to.shared.u64 t, %1; cvt.u32.u64 %0, t; }" : "=r"(a) : "l"(p));
    return a;
}
__device__ __forceinline__ void ldsm4(uint32_t* r, uint32_t addr) {
    asm volatile("ldmatrix.sync.aligned.m8n8.x4.shared.b16 {%0,%1,%2,%3}, [%4];"
                 : "=r"(r[0]), "=r"(r[1]), "=r"(r[2]), "=r"(r[3]) : "r"(addr));
}
__device__ __forceinline__ void ldsm4t(uint32_t* r, uint32_t addr) {
    asm volatile("ldmatrix.sync.aligned.m8n8.x4.trans.shared.b16 {%0,%1,%2,%3}, [%4];"
                 : "=r"(r[0]), "=r"(r[1]), "=r"(r[2]), "=r"(r[3]) : "r"(addr));
}
__device__ __forceinline__ void mma16816(float* d, const uint32_t* a, const uint32_t* b) {
    asm volatile(
        "mma.sync.aligned.m16n8k16.row.col.f32.f16.f16.f32 "
        "{%0,%1,%2,%3}, {%4,%5,%6,%7}, {%8,%9}, {%0,%1,%2,%3};"
        : "+f"(d[0]), "+f"(d[1]), "+f"(d[2]), "+f"(d[3])
        : "r"(a[0]), "r"(a[1]), "r"(a[2]), "r"(a[3]), "r"(b[0]), "r"(b[1]));
}

// One 64x64x64 unit (3-term split): warp handles m16 tile (rows 16*wid..+16).
__device__ __forceinline__ void unit_mma(float (&acc)[8][4],
                                         uint32_t sA, uint32_t sB,
                                         int wid, int lane) {
    const int arow = 16 * wid + (lane & 15);
    const uint32_t axr = (uint32_t)((arow & 7) << 4);
    const uint32_t aseg = (uint32_t)((lane >> 4) << 4);
    const int brow_l = lane & 15;
    const uint32_t bxr = (uint32_t)((brow_l & 7) << 4);
    const uint32_t bseg = (uint32_t)(lane >> 4);
#pragma unroll
    for (int kt = 0; kt < 4; kt++) {
        uint32_t ah[4], al[4];
        const uint32_t acol = (uint32_t)(kt * 32) + aseg;
        ldsm4(ah, sA + (uint32_t)arow * 256 + (acol ^ axr));
        ldsm4(al, sA + (uint32_t)arow * 256 + ((128 + acol) ^ axr));
        const uint32_t brow = (uint32_t)(kt * 16 + brow_l);
#pragma unroll
        for (int np = 0; np < 4; np++) {
            uint32_t bh[4], bl[4];
            const uint32_t bnb = (uint32_t)((2 * np + bseg) << 4);
            ldsm4t(bh, sB + brow * 128 + (bnb ^ bxr));
            ldsm4t(bl, sB + (brow + 64) * 128 + (bnb ^ bxr));
            mma16816(acc[2 * np],     ah, bh);
            mma16816(acc[2 * np],     al, bh);
            mma16816(acc[2 * np],     ah, bl);
            mma16816(acc[2 * np + 1], ah, bh + 2);
            mma16816(acc[2 * np + 1], al, bh + 2);
            mma16816(acc[2 * np + 1], ah, bl + 2);
        }
    }
}

// ---------------------------------------------------------------------------
// pac: block = 8h x 16w output tile (fixed h-parity, both w-parities).
//   Per tap-unit: build A (64 active px x 64c, split fp16 hi/lo), copy B image,
//   4 warps each do one m16 x n64 x k64 x 3-term MMA chain.
// SMEM: A 16KB @0, B 16KB @16384, bias @32768; epilogue reuses [0,32KB) as Cs.
// ---------------------------------------------------------------------------
__global__ __launch_bounds__(128)
void pac_kernel(const float* __restrict__ x,
                const float* __restrict__ bias,
                float* __restrict__ out) {
    __shared__ __align__(256) char smem[16384 + 16384 + 256];
    const uint32_t sb = smem_u32(smem);
    const int t = threadIdx.x;
    const int lane = t & 31, wid = t >> 5;

    float* biasSm = (float*)(smem + 32768);
    if (t < 64) biasSm[t] = bias[t];

    // LPT: ph=1 blocks (6 units) first, ph=0 (3 units) last
    const int bid = blockIdx.x;
    const int ph = (bid < 1024) ? 1 : 0;
    const int sub = bid & 1023;
    const int b = sub >> 8;
    const int tile = sub & 255;
    const int hh0 = (tile >> 4) * 8;   // h-parity row block
    const int ww0 = (tile & 15) * 16;  // contiguous w block

    // A-build identity: row r = t&63 (i = r>>3 h-row, jw = r&7 w-col), half = t>>6
    const int r = t & 63, half = t >> 6;
    const int ii = r >> 3, jw = r & 7;
    const int h = 2 * (hh0 + ii) + ph;

    float acc0[8][4], acc1[8][4];
#pragma unroll
    for (int i = 0; i < 8; i++)
#pragma unroll
        for (int j = 0; j < 4; j++) { acc0[i][j] = 0.f; acc1[i][j] = 0.f; }

    const int nkh = ph ? 2 : 1;
    for (int ta = 0; ta < nkh; ta++) {
        const int kh = ph ? ta * 2 : 1;
        const int dh = (kh == 2) ? 1 : 0;
#pragma unroll
        for (int kw = 0; kw < 3; kw++) {
            const int wpar = (kw == 1) ? 0 : 1;
            const int dw = (kw == 2) ? 1 : 0;
            const int tap = kh * 3 + kw;

            // --- B copy: 16KB pre-swizzled [k][n] image -> smem ---
            {
                const uint4* src = (const uint4*)((const char*)g_wb + (size_t)tap * 16384);
                uint4* dst = (uint4*)(smem + 16384);
#pragma unroll
                for (int q = 0; q < 8; q++) dst[t + q * 128] = src[t + q * 128];
            }
            // --- A build: row r = kv*x split into fp16 hi (k 0-63) / lo (k 64-127) ---
            {
                int ih = hh0 + ii + dh;
                int iw = (ww0 >> 1) + jw + dw;
                const bool inb = (ih < HIN) && (iw < WIN);
                const int wout = ww0 + 2 * jw + wpar;
                float kv = 0.f;
                if (inb) kv = g_kern[(((size_t)b * 9 + tap) * GHH + h) * GWW + wout];
                else { ih = 0; iw = 0; }
                const float* xp = x + (((size_t)b * CIN) * HIN + ih) * WIN + iw;
                const uint32_t rowbase = (uint32_t)r * 256;
                const uint32_t xr = (uint32_t)((r & 7) << 4);
#pragma unroll
                for (int cg = 0; cg < 4; cg++) {
                    const int c0 = half * 32 + cg * 8;
                    uint32_t hi[4], lo[4];
#pragma unroll
                    for (int u = 0; u < 4; u++) {
                        float v0 = kv * __ldg(xp + (size_t)(c0 + 2 * u) * HW);
                        float v1 = kv * __ldg(xp + (size_t)(c0 + 2 * u + 1) * HW);
                        __half2 h2 = __floats2half2_rn(v0, v1);
                        float2 hb = __half22float2(h2);
                        __half2 l2 = __floats2half2_rn(v0 - hb.x, v1 - hb.y);
                        hi[u] = *(uint32_t*)&h2;
                        lo[u] = *(uint32_t*)&l2;
                    }
                    const uint32_t offh = rowbase + (((uint32_t)(c0 * 2)) ^ xr);
                    const uint32_t offl = rowbase + (((uint32_t)(128 + c0 * 2)) ^ xr);
                    *(uint4*)(smem + offh) = make_uint4(hi[0], hi[1], hi[2], hi[3]);
                    *(uint4*)(smem + offl) = make_uint4(lo[0], lo[1], lo[2], lo[3]);
                }
            }
            __syncthreads();

            if (kw == 1) unit_mma(acc0, sb, sb + 16384, wid, lane);
            else         unit_mma(acc1, sb, sb + 16384, wid, lane);
            __syncthreads();
        }
    }

    // --- epilogue: stage transposed to smem (32-bank swizzle), coalesced store ---
    float* Cs = (float*)smem;
#pragma unroll
    for (int w2 = 0; w2 < 2; w2++) {
#pragma unroll
        for (int nt = 0; nt < 8; nt++) {
#pragma unroll
            for (int e = 0; e < 4; e++) {
                const float v = w2 ? acc1[nt][e] : acc0[nt][e];
                const int o = nt * 8 + 2 * (lane & 3) + (e & 1);
                const int mrow = (lane >> 2) + 8 * (e >> 1);
                const int px = (2 * wid + (mrow >> 3)) * 16 + (mrow & 7) * 2 + w2;
                const int sw = ((o >> 1) & 1) | (((o >> 2) & 1) << 4);
                Cs[o * 128 + (px ^ sw)] = v;
            }
        }
    }
    __syncthreads();

    float* op = out + (((size_t)b * COUT) * GHH + (2 * (hh0 + (t >> 4)) + ph)) * GWW + ww0 + (t & 15);
#pragma unroll 8
    for (int o = 0; o < COUT; o++) {
        const int sw = ((o >> 1) & 1) | (((o >> 2) & 1) << 4);
        op[(size_t)o * GHH * GWW] = Cs[o * 128 + (t ^ sw)] + biasSm[o];
    }
}

// ---------------------------------------------------------------------------
extern "C" void kernel_launch(void* const* d_in, const int* in_sizes, int n_in,
                              void* d_out, int out_size) {
    const float* x      = (const float*)d_in[0];
    const float* guide  = (const float*)d_in[1];
    const float* weight = (const float*)d_in[2];
    const float* bias   = (const float*)d_in[3];
    float* out          = (float*)d_out;

    prep_kernel<<<1168, 256>>>(guide, weight);
    pac_kernel<<<2048, 128>>>(x, bias, out);
}

// round 5
// speedup vs baseline: 1.9067x; 1.1526x over previous
#include <cuda_runtime.h>
#include <cuda_fp16.h>
#include <cstdint>

#define BATCH 4
#define CIN   64
#define COUT  64
#define HIN   128
#define WIN   128
#define GHH   256
#define GWW   256
#define HW    (HIN * WIN)

// Scratch
__device__ float  g_kern[(size_t)BATCH * 9 * GHH * GWW];  // Gaussian affinities (valid-parity entries only)
__device__ __half g_wb[9 * 64 * 64];                      // per-tap B image: [k=0..63][n=64] fp16-hi, 128B rows, XOR-swizzled

// ---------------------------------------------------------------------------
// Prep: blocks [0,1024) -> Gaussian kernel (only parity-valid taps);
//       blocks [1024,1168) -> fp16 weight images (hi part only; A carries the
//       2-term split: ah*bh + al*bh)
// ---------------------------------------------------------------------------
__global__ void prep_kernel(const float* __restrict__ guide,
                            const float* __restrict__ weight) {
    if (blockIdx.x < 1024) {
        int idx = blockIdx.x * 256 + threadIdx.x;
        int w = idx % GWW;
        int h = (idx / GWW) % GHH;
        int b = idx / (GHH * GWW);
        const float* gp = guide + (size_t)b * 3 * GHH * GWW;
        float c0 = gp[0 * GHH * GWW + h * GWW + w];
        float c1 = gp[1 * GHH * GWW + h * GWW + w];
        float c2 = gp[2 * GHH * GWW + h * GWW + w];
#pragma unroll
        for (int kh = 0; kh < 3; kh++) {
#pragma unroll
            for (int kw = 0; kw < 3; kw++) {
                if ((((h + kh) & 1) == 0) || (((w + kw) & 1) == 0)) continue;  // tap never used
                int hh = h + kh - 1, ww = w + kw - 1;
                float v0 = 0.f, v1 = 0.f, v2 = 0.f;
                if (hh >= 0 && hh < GHH && ww >= 0 && ww < GWW) {
                    v0 = gp[0 * GHH * GWW + hh * GWW + ww];
                    v1 = gp[1 * GHH * GWW + hh * GWW + ww];
                    v2 = gp[2 * GHH * GWW + hh * GWW + ww];
                }
                float d0 = v0 - c0, d1 = v1 - c1, d2 = v2 - c2;
                float s = d0 * d0 + d1 * d1 + d2 * d2;
                g_kern[(((size_t)b * 9 + kh * 3 + kw) * GHH + h) * GWW + w] = __expf(-0.5f * s);
            }
        }
    } else {
        int idx = (blockIdx.x - 1024) * 256 + threadIdx.x;
        if (idx < 9 * 64 * 64) {
            int tap = idx % 9;
            int o = (idx / 9) & 63;
            int c = idx / (9 * 64);
            float wv = weight[((size_t)c * COUT + o) * 9 + tap];
            __half bh = __float2half_rn(wv);
            // B image: [k-row][n], 128B rows, byte-in-row = (2o) ^ ((krow&7)<<4)
            char* p = (char*)g_wb + (size_t)tap * 8192;
            uint32_t col = ((uint32_t)o * 2) ^ (((uint32_t)c & 7) << 4);
            *(__half*)(p + (uint32_t)c * 128 + col) = bh;
        }
    }
}

// ---------------------------------------------------------------------------
// mma helpers
// ---------------------------------------------------------------------------
__device__ __forceinline__ uint32_t smem_u32(const void* p) {
    uint32_t a;
    asm("{ .reg .u64 t; cvta.to.shared.u64 t, %1; cvt.u32.u64 %0, t; }" : "=r"(a) : "l"(p));
    return a;
}
__device__ __forceinline__ void ldsm4(uint32_t* r, uint32_t addr) {
    asm volatile("ldmatrix.sync.aligned.m8n8.x4.shared.b16 {%0,%1,%2,%3}, [%4];"
                 : "=r"(r[0]), "=r"(r[1]), "=r"(r[2]), "=r"(r[3]) : "r"(addr));
}
__device__ __forceinline__ void ldsm4t(uint32_t* r, uint32_t addr) {
    asm volatile("ldmatrix.sync.aligned.m8n8.x4.trans.shared.b16 {%0,%1,%2,%3}, [%4];"
                 : "=r"(r[0]), "=r"(r[1]), "=r"(r[2]), "=r"(r[3]) : "r"(addr));
}
__device__ __forceinline__ void mma16816(float* d, const uint32_t* a, const uint32_t* b) {
    asm volatile(
        "mma.sync.aligned.m16n8k16.row.col.f32.f16.f16.f32 "
        "{%0,%1,%2,%3}, {%4,%5,%6,%7}, {%8,%9}, {%0,%1,%2,%3};"
        : "+f"(d[0]), "+f"(d[1]), "+f"(d[2]), "+f"(d[3])
        : "r"(a[0]), "r"(a[1]), "r"(a[2]), "r"(a[3]), "r"(b[0]), "r"(b[1]));
}

// One 64x64x64 unit (2-term split): warp handles m16 tile (rows 16*wid..+16).
// bh fragment loaded once per (kt,np) and reused for both ah and al terms.
__device__ __forceinline__ void unit_mma(float (&acc)[8][4],
                                         uint32_t sA, uint32_t sB,
                                         int wid, int lane) {
    const int arow = 16 * wid + (lane & 15);
    const uint32_t axr = (uint32_t)((arow & 7) << 4);
    const uint32_t aseg = (uint32_t)((lane >> 4) << 4);
    const int brow_l = lane & 15;
    const uint32_t bxr = (uint32_t)((brow_l & 7) << 4);
    const uint32_t bseg = (uint32_t)(lane >> 4);
#pragma unroll
    for (int kt = 0; kt < 4; kt++) {
        uint32_t ah[4], al[4];
        const uint32_t acol = (uint32_t)(kt * 32) + aseg;
        ldsm4(ah, sA + (uint32_t)arow * 256 + (acol ^ axr));
        ldsm4(al, sA + (uint32_t)arow * 256 + ((128 + acol) ^ axr));
        const uint32_t brow = (uint32_t)(kt * 16 + brow_l);
#pragma unroll
        for (int np = 0; np < 4; np++) {
            uint32_t bh[4];
            const uint32_t bnb = (uint32_t)((2 * np + bseg) << 4);
            ldsm4t(bh, sB + brow * 128 + (bnb ^ bxr));
            mma16816(acc[2 * np],     ah, bh);
            mma16816(acc[2 * np],     al, bh);
            mma16816(acc[2 * np + 1], ah, bh + 2);
            mma16816(acc[2 * np + 1], al, bh + 2);
        }
    }
}

// ---------------------------------------------------------------------------
// pac: block = 8h x 16w output tile (fixed h-parity, both w-parities).
//   Per tap-unit: build A (64 active px x 64c, split fp16 hi/lo), copy B image,
//   4 warps each do one m16 x n64 x k64 x 2-term MMA chain.
// SMEM: A 16KB @0, B 8KB @16384, bias @32768; epilogue reuses [0,32KB) as Cs.
// ---------------------------------------------------------------------------
__global__ __launch_bounds__(128)
void pac_kernel(const float* __restrict__ x,
                const float* __restrict__ bias,
                float* __restrict__ out) {
    __shared__ __align__(256) char smem[32768 + 256];
    const uint32_t sb = smem_u32(smem);
    const int t = threadIdx.x;
    const int lane = t & 31, wid = t >> 5;

    float* biasSm = (float*)(smem + 32768);
    if (t < 64) biasSm[t] = bias[t];

    // LPT: ph=1 blocks (6 units) first, ph=0 (3 units) last
    const int bid = blockIdx.x;
    const int ph = (bid < 1024) ? 1 : 0;
    const int sub = bid & 1023;
    const int b = sub >> 8;
    const int tile = sub & 255;
    const int hh0 = (tile >> 4) * 8;   // h-parity row block
    const int ww0 = (tile & 15) * 16;  // contiguous w block

    // A-build identity: row r = t&63 (i = r>>3 h-row, jw = r&7 w-col), half = t>>6
    const int r = t & 63, half = t >> 6;
    const int ii = r >> 3, jw = r & 7;
    const int h = 2 * (hh0 + ii) + ph;

    float acc0[8][4], acc1[8][4];
#pragma unroll
    for (int i = 0; i < 8; i++)
#pragma unroll
        for (int j = 0; j < 4; j++) { acc0[i][j] = 0.f; acc1[i][j] = 0.f; }

    const int nkh = ph ? 2 : 1;
    for (int ta = 0; ta < nkh; ta++) {
        const int kh = ph ? ta * 2 : 1;
        const int dh = (kh == 2) ? 1 : 0;
#pragma unroll
        for (int kw = 0; kw < 3; kw++) {
            const int wpar = (kw == 1) ? 0 : 1;
            const int dw = (kw == 2) ? 1 : 0;
            const int tap = kh * 3 + kw;

            // --- B copy: 8KB pre-swizzled [k][n] image -> smem ---
            {
                const uint4* src = (const uint4*)((const char*)g_wb + (size_t)tap * 8192);
                uint4* dst = (uint4*)(smem + 16384);
#pragma unroll
                for (int q = 0; q < 4; q++) dst[t + q * 128] = src[t + q * 128];
            }
            // --- A build: row r = kv*x split into fp16 hi (k 0-63) / lo (k 64-127) ---
            {
                int ih = hh0 + ii + dh;
                int iw = (ww0 >> 1) + jw + dw;
                const bool inb = (ih < HIN) && (iw < WIN);
                const int wout = ww0 + 2 * jw + wpar;
                float kv = 0.f;
                if (inb) kv = g_kern[(((size_t)b * 9 + tap) * GHH + h) * GWW + wout];
                else { ih = 0; iw = 0; }
                const float* xp = x + (((size_t)b * CIN) * HIN + ih) * WIN + iw;
                const uint32_t rowbase = (uint32_t)r * 256;
                const uint32_t xr = (uint32_t)((r & 7) << 4);
#pragma unroll
                for (int cg = 0; cg < 4; cg++) {
                    const int c0 = half * 32 + cg * 8;
                    uint32_t hi[4], lo[4];
#pragma unroll
                    for (int u = 0; u < 4; u++) {
                        float v0 = kv * __ldg(xp + (size_t)(c0 + 2 * u) * HW);
                        float v1 = kv * __ldg(xp + (size_t)(c0 + 2 * u + 1) * HW);
                        __half2 h2 = __floats2half2_rn(v0, v1);
                        float2 hb = __half22float2(h2);
                        __half2 l2 = __floats2half2_rn(v0 - hb.x, v1 - hb.y);
                        hi[u] = *(uint32_t*)&h2;
                        lo[u] = *(uint32_t*)&l2;
                    }
                    const uint32_t offh = rowbase + (((uint32_t)(c0 * 2)) ^ xr);
                    const uint32_t offl = rowbase + (((uint32_t)(128 + c0 * 2)) ^ xr);
                    *(uint4*)(smem + offh) = make_uint4(hi[0], hi[1], hi[2], hi[3]);
                    *(uint4*)(smem + offl) = make_uint4(lo[0], lo[1], lo[2], lo[3]);
                }
            }
            __syncthreads();

            if (kw == 1) unit_mma(acc0, sb, sb + 16384, wid, lane);
            else         unit_mma(acc1, sb, sb + 16384, wid, lane);
            __syncthreads();
        }
    }

    // --- epilogue: stage transposed to smem (32-bank swizzle), coalesced store ---
    float* Cs = (float*)smem;
#pragma unroll
    for (int w2 = 0; w2 < 2; w2++) {
#pragma unroll
        for (int nt = 0; nt < 8; nt++) {
#pragma unroll
            for (int e = 0; e < 4; e++) {
                const float v = w2 ? acc1[nt][e] : acc0[nt][e];
                const int o = nt * 8 + 2 * (lane & 3) + (e & 1);
                const int mrow = (lane >> 2) + 8 * (e >> 1);
                const int px = (2 * wid + (mrow >> 3)) * 16 + (mrow & 7) * 2 + w2;
                const int sw = ((o >> 1) & 1) | (((o >> 2) & 1) << 4);
                Cs[o * 128 + (px ^ sw)] = v;
            }
        }
    }
    __syncthreads();

    float* op = out + (((size_t)b * COUT) * GHH + (2 * (hh0 + (t >> 4)) + ph)) * GWW + ww0 + (t & 15);
#pragma unroll 8
    for (int o = 0; o < COUT; o++) {
        const int sw = ((o >> 1) & 1) | (((o >> 2) & 1) << 4);
        op[(size_t)o * GHH * GWW] = Cs[o * 128 + (t ^ sw)] + biasSm[o];
    }
}

// ---------------------------------------------------------------------------
extern "C" void kernel_launch(void* const* d_in, const int* in_sizes, int n_in,
                              void* d_out, int out_size) {
    const float* x      = (const float*)d_in[0];
    const float* guide  = (const float*)d_in[1];
    const float* weight = (const float*)d_in[2];
    const float* bias   = (const float*)d_in[3];
    float* out          = (float*)d_out;

    prep_kernel<<<1168, 256>>>(guide, weight);
    pac_kernel<<<2048, 128>>>(x, bias, out);
}